// round 3
// baseline (speedup 1.0000x reference)
#include <cuda_runtime.h>
#include <cstdint>

// SubsampledRelativeAttention (closed form validated R1/R2):
//   h = b % 8, c = t >> 2,  E = [e1 ; e2[1:]] (511 rows)
//   out[b,t,s] = q[b,t] . E[h, j],  j = 255 - c + s
// Banded GEMM on mma.sync m16n8k8 TF32. Output rows are DENSE in s, so
// results are staged in smem (scattered conflict-free STS) and flushed
// with fully coalesced STG.128.

#define TT 1024
#define SS 256
#define DD 64

constexpr int TM   = 64;        // t rows per CTA
constexpr int JC   = 64;        // E-rows per chunk
constexpr int NCH  = 5;         // 5*64 = 320 >= 271 band width
constexpr int STR  = DD + 4;    // 68: Q/E smem row stride
constexpr int STRO = SS + 8;    // 264: out-stage stride (≡8 mod 32 -> conflict-free STS)
constexpr int SMEM_BYTES = (TM * STR + JC * STR) * 4 + TM * STRO * 4;  // 102400

__device__ __forceinline__ uint32_t f2tf32(float x) {
    uint32_t r;
    asm("cvt.rna.tf32.f32 %0, %1;" : "=r"(r) : "f"(x));
    return r;
}

__global__ __launch_bounds__(256, 2)
void srel_tf32_kernel(const float* __restrict__ q,
                      const float* __restrict__ e1,
                      const float* __restrict__ e2,
                      float* __restrict__ out)
{
    extern __shared__ __align__(16) char smem[];
    uint32_t* Qs   = reinterpret_cast<uint32_t*>(smem);            // [64][68] tf32
    uint32_t* Es   = Qs + TM * STR;                                // [64][68] tf32
    float*    Outs = reinterpret_cast<float*>(Es + JC * STR);      // [64][264]

    const int blk  = blockIdx.x;
    const int b    = blk >> 4;            // 16 t-tiles per batch row
    const int t0   = (blk & 15) * TM;
    const int h    = b & 7;
    const int c0   = t0 >> 2;
    const int jbase = 240 - c0;           // min j over tile (c spans c0..c0+15)

    const int tid  = threadIdx.x;
    const int wid  = tid >> 5;
    const int lane = tid & 31;
    const int wt   = wid >> 2;            // 0..1: t rows [wt*32, +32)
    const int wj   = wid & 3;             // 0..3: j cols [wj*16, +16)
    const int r    = lane >> 2;           // 0..7
    const int cidx = lane & 3;            // 0..3

    // ---- Q tile (64 x 64) -> smem tf32, coalesced ----
    const float* qb = q + ((size_t)b * TT + t0) * DD;
    for (int i = tid; i < TM * DD; i += 256) {
        const int tt = i >> 6, k = i & 63;
        Qs[tt * STR + k] = f2tf32(qb[i]);
    }

    const float* e1h = e1 + (size_t)h * SS * DD;
    const float* e2h = e2 + (size_t)h * SS * DD;

    const uint32_t* Aq = Qs + (wt * 32 + r) * STR + cidx;
    const uint32_t* Be = Es + (wj * 16 + r) * STR + cidx;

    for (int ch = 0; ch < NCH; ch++) {
        const int jc = jbase + ch * JC;

        __syncthreads();   // prior mma done reading Es; Qs ready (iter 0)

        // ---- E chunk (64 x 64) -> smem tf32 ----
        for (int i = tid; i < JC * DD; i += 256) {
            const int jj = i >> 6, k = i & 63;
            const int j  = jc + jj;
            const float* src;
            if (j <= 255) {
                src = e1h + (size_t)j * DD;          // E rows [0,255] = e1
            } else {
                int j2 = j - 255;                    // E rows [256,510] = e2[1:]
                if (j2 > 255) j2 = 255;              // overrun rows never stored
                src = e2h + (size_t)j2 * DD;
            }
            Es[jj * STR + k] = f2tf32(src[k]);
        }
        __syncthreads();

        // ---- warp 32x16 tile: 2 m-frags x 2 n-frags, K=64 in 8 steps ----
        float acc[2][2][4];
        #pragma unroll
        for (int mt = 0; mt < 2; mt++)
            #pragma unroll
            for (int nt = 0; nt < 2; nt++)
                #pragma unroll
                for (int v = 0; v < 4; v++)
                    acc[mt][nt][v] = 0.0f;

        #pragma unroll
        for (int ks = 0; ks < 8; ks++) {
            const int k0 = ks * 8;
            uint32_t a[2][4], bf[2][2];
            #pragma unroll
            for (int mt = 0; mt < 2; mt++) {
                const uint32_t* p = Aq + mt * 16 * STR + k0;
                a[mt][0] = p[0];
                a[mt][1] = p[8 * STR];
                a[mt][2] = p[4];
                a[mt][3] = p[8 * STR + 4];
            }
            #pragma unroll
            for (int nt = 0; nt < 2; nt++) {
                const uint32_t* p = Be + nt * 8 * STR + k0;
                bf[nt][0] = p[0];
                bf[nt][1] = p[4];
            }
            #pragma unroll
            for (int mt = 0; mt < 2; mt++)
                #pragma unroll
                for (int nt = 0; nt < 2; nt++)
                    asm volatile(
                        "mma.sync.aligned.m16n8k8.row.col.f32.tf32.tf32.f32 "
                        "{%0,%1,%2,%3}, {%4,%5,%6,%7}, {%8,%9}, {%0,%1,%2,%3};"
                        : "+f"(acc[mt][nt][0]), "+f"(acc[mt][nt][1]),
                          "+f"(acc[mt][nt][2]), "+f"(acc[mt][nt][3])
                        : "r"(a[mt][0]), "r"(a[mt][1]), "r"(a[mt][2]), "r"(a[mt][3]),
                          "r"(bf[nt][0]), "r"(bf[nt][1]));
        }

        // ---- banded scatter into smem out-stage (conflict-free STS.32) ----
        #pragma unroll
        for (int mt = 0; mt < 2; mt++) {
            #pragma unroll
            for (int half = 0; half < 2; half++) {
                const int row = wt * 32 + mt * 16 + half * 8 + r;
                const int c   = (t0 + row) >> 2;
                const int sb  = jc + wj * 16 + 2 * cidx - 255 + c;
                float* orow = Outs + row * STRO;
                #pragma unroll
                for (int nt = 0; nt < 2; nt++) {
                    const int s = sb + nt * 8;
                    const float v0 = acc[mt][nt][half * 2 + 0];
                    const float v1 = acc[mt][nt][half * 2 + 1];
                    if ((unsigned)s < (unsigned)SS)       orow[s]     = v0;
                    if ((unsigned)(s + 1) < (unsigned)SS) orow[s + 1] = v1;
                }
            }
        }
    }

    __syncthreads();

    // ---- coalesced flush: smem -> gmem as float4 ----
    float* ob = out + ((size_t)b * TT + t0) * SS;
    #pragma unroll
    for (int i = tid; i < TM * (SS / 4); i += 256) {
        const int row = i >> 6;
        const int c4  = (i & 63) << 2;
        const float4 v = *reinterpret_cast<const float4*>(Outs + row * STRO + c4);
        *reinterpret_cast<float4*>(ob + row * SS + c4) = v;
    }
}

extern "C" void kernel_launch(void* const* d_in, const int* in_sizes, int n_in,
                              void* d_out, int out_size)
{
    const float* q  = (const float*)d_in[0];
    const float* e1 = (const float*)d_in[1];
    const float* e2 = (const float*)d_in[2];
    float* out      = (float*)d_out;

    cudaFuncSetAttribute(srel_tf32_kernel,
                         cudaFuncAttributeMaxDynamicSharedMemorySize, SMEM_BYTES);
    srel_tf32_kernel<<<128 * (TT / TM), 256, SMEM_BYTES>>>(q, e1, e2, out);
}

// round 5
// speedup vs baseline: 1.7427x; 1.7427x over previous
#include <cuda_runtime.h>
#include <cstdint>

// SubsampledRelativeAttention (closed form, validated R1-R3):
//   h = b % 8, c = t >> 2, E = [e1 ; e2[1:]] (511 rows)
//   out[b,t,s] = q[b,t] . E[h, j],  j = 255 - c + s
// mma.sync m16n8k8 TF32 banded GEMM. Per-chunk results staged in a small
// 64x64 smem tile (STS.64), flushed row-dense with coalesced STG.32.

#define TT 1024
#define SS 256
#define DD 64

constexpr int TM  = 64;       // t rows per CTA
constexpr int JC  = 64;       // E rows per chunk
constexpr int NCH = 5;        // 5*64 = 320 >= 271 band width (c spans 16)
constexpr int STR = 68;       // smem row stride (words): conflict-free frags
constexpr int SMEM_BYTES = (TM * STR + JC * STR + TM * STR) * 4;  // 52224

__device__ __forceinline__ uint32_t f2tf32(float x) {
    uint32_t r;
    asm("cvt.rna.tf32.f32 %0, %1;" : "=r"(r) : "f"(x));
    return r;
}

__global__ __launch_bounds__(128, 4)
void srel_tf32_kernel(const float* __restrict__ q,
                      const float* __restrict__ e1,
                      const float* __restrict__ e2,
                      float* __restrict__ out)
{
    extern __shared__ __align__(16) uint32_t smem[];
    uint32_t* Qs = smem;                       // [64][68] tf32
    uint32_t* Es = smem + TM * STR;            // [64][68] tf32
    float*    St = reinterpret_cast<float*>(smem + TM * STR + JC * STR); // [64][68]

    const int blk  = blockIdx.x;
    const int b    = blk >> 4;            // 16 t-tiles per batch row
    const int t0   = (blk & 15) * TM;
    const int h    = b & 7;
    const int c0   = t0 >> 2;
    const int jbase = 240 - c0;           // min j over tile (c spans c0..c0+15)

    const int tid  = threadIdx.x;
    const int wid  = tid >> 5;
    const int lane = tid & 31;
    const int wt   = wid >> 1;            // t-half: rows [wt*32, +32)
    const int wj   = wid & 1;             // j-half: cols [wj*32, +32)
    const int r    = lane >> 2;
    const int cidx = lane & 3;

    // ---- Q tile (64 x 64) -> smem tf32, float4 loads ----
    const float4* qb4 = reinterpret_cast<const float4*>(
                            q + ((size_t)b * TT + t0) * DD);
    for (int i = tid; i < TM * DD / 4; i += 128) {
        const int row = i >> 4;          // 16 float4 per row
        const int k4  = (i & 15) << 2;
        const float4 v = qb4[i];
        uint4 u;
        u.x = f2tf32(v.x); u.y = f2tf32(v.y);
        u.z = f2tf32(v.z); u.w = f2tf32(v.w);
        *reinterpret_cast<uint4*>(Qs + row * STR + k4) = u;
    }

    const float4* e1h = reinterpret_cast<const float4*>(e1 + (size_t)h * SS * DD);
    const float4* e2h = reinterpret_cast<const float4*>(e2 + (size_t)h * SS * DD);

    const uint32_t* Aq = Qs + (wt * 32 + r) * STR + cidx;
    const uint32_t* Be = Es + (wj * 32 + r) * STR + cidx;

    for (int ch = 0; ch < NCH; ch++) {
        const int jc = jbase + ch * JC;

        __syncthreads();   // stage flushed, Es free

        // ---- E chunk (64 x 64) -> smem tf32, float4 loads ----
        for (int i = tid; i < JC * DD / 4; i += 128) {
            const int jj = i >> 4;
            const int k4 = (i & 15) << 2;
            const int j  = jc + jj;
            float4 v;
            if (j <= 255) {
                v = e1h[j * 16 + (k4 >> 2)];          // E rows [0,255] = e1
            } else {
                int j2 = j - 255;                     // E rows [256,510] = e2[1:]
                if (j2 > 255) j2 = 255;               // overrun rows never flushed
                v = e2h[j2 * 16 + (k4 >> 2)];
            }
            uint4 u;
            u.x = f2tf32(v.x); u.y = f2tf32(v.y);
            u.z = f2tf32(v.z); u.w = f2tf32(v.w);
            *reinterpret_cast<uint4*>(Es + jj * STR + k4) = u;
        }
        __syncthreads();

        // ---- warp 32x32 tile: 2 m-frags x 4 n-frags, K=64 in 8 steps ----
        float acc[2][4][4];
        #pragma unroll
        for (int mt = 0; mt < 2; mt++)
            #pragma unroll
            for (int nt = 0; nt < 4; nt++)
                #pragma unroll
                for (int v = 0; v < 4; v++)
                    acc[mt][nt][v] = 0.0f;

        #pragma unroll
        for (int ks = 0; ks < 8; ks++) {
            const int k0 = ks * 8;
            uint32_t a[2][4], bf[4][2];
            #pragma unroll
            for (int mt = 0; mt < 2; mt++) {
                const uint32_t* p = Aq + mt * 16 * STR + k0;
                a[mt][0] = p[0];
                a[mt][1] = p[8 * STR];
                a[mt][2] = p[4];
                a[mt][3] = p[8 * STR + 4];
            }
            #pragma unroll
            for (int nt = 0; nt < 4; nt++) {
                const uint32_t* p = Be + nt * 8 * STR + k0;
                bf[nt][0] = p[0];
                bf[nt][1] = p[4];
            }
            #pragma unroll
            for (int mt = 0; mt < 2; mt++)
                #pragma unroll
                for (int nt = 0; nt < 4; nt++)
                    asm volatile(
                        "mma.sync.aligned.m16n8k8.row.col.f32.tf32.tf32.f32 "
                        "{%0,%1,%2,%3}, {%4,%5,%6,%7}, {%8,%9}, {%0,%1,%2,%3};"
                        : "+f"(acc[mt][nt][0]), "+f"(acc[mt][nt][1]),
                          "+f"(acc[mt][nt][2]), "+f"(acc[mt][nt][3])
                        : "r"(a[mt][0]), "r"(a[mt][1]), "r"(a[mt][2]), "r"(a[mt][3]),
                          "r"(bf[nt][0]), "r"(bf[nt][1]));
        }

        // ---- stage: St[row][jj] via STS.64 (v0,v1 adjacent in jj) ----
        #pragma unroll
        for (int mt = 0; mt < 2; mt++) {
            #pragma unroll
            for (int half = 0; half < 2; half++) {
                const int row = wt * 32 + mt * 16 + half * 8 + r;
                float* srow = St + row * STR + wj * 32 + 2 * cidx;
                #pragma unroll
                for (int nt = 0; nt < 4; nt++) {
                    float2 v;
                    v.x = acc[mt][nt][half * 2 + 0];
                    v.y = acc[mt][nt][half * 2 + 1];
                    *reinterpret_cast<float2*>(srow + nt * 8) = v;
                }
            }
        }
        __syncthreads();

        // ---- coalesced flush: warp owns 16 rows; lane = s offset ----
        #pragma unroll
        for (int i = 0; i < 16; i++) {
            const int row  = wid * 16 + i;
            const int c    = (t0 + row) >> 2;
            const int srow = jc + c - 255;
            if (srow >= SS || srow + JC <= 0) continue;
            const float v0 = St[row * STR + lane];
            const float v1 = St[row * STR + 32 + lane];
            const int s0 = srow + lane;
            const int s1 = s0 + 32;
            float* og = out + ((size_t)b * TT + t0 + row) * SS;
            if ((unsigned)s0 < (unsigned)SS) og[s0] = v0;
            if ((unsigned)s1 < (unsigned)SS) og[s1] = v1;
        }
    }
}

extern "C" void kernel_launch(void* const* d_in, const int* in_sizes, int n_in,
                              void* d_out, int out_size)
{
    const float* q  = (const float*)d_in[0];
    const float* e1 = (const float*)d_in[1];
    const float* e2 = (const float*)d_in[2];
    float* out      = (float*)d_out;

    cudaFuncSetAttribute(srel_tf32_kernel,
                         cudaFuncAttributeMaxDynamicSharedMemorySize, SMEM_BYTES);
    srel_tf32_kernel<<<128 * (TT / TM), 128, SMEM_BYTES>>>(q, e1, e2, out);
}

// round 6
// speedup vs baseline: 1.9365x; 1.1112x over previous
#include <cuda_runtime.h>
#include <cstdint>

// SubsampledRelativeAttention (closed form, validated R1-R5):
//   h = b % 8, c = t >> 2, E = [e1 ; e2[1:]] (511 rows)
//   out[b,t,s] = q[b,t] . E[h, j],  j = 255 - c + s
// mma.sync m16n8k8 TF32 banded GEMM. E chunks are prefetched with cp.async
// overlapped with the stage+flush epilogue; per-chunk results staged in a
// 64x64 smem tile and flushed row-dense with coalesced STG.
// Qs holds pre-converted tf32; Es holds raw f32 (cvt at B-frag load).

#define TT 1024
#define SS 256
#define DD 64

constexpr int TM  = 64;       // t rows per CTA
constexpr int JC  = 64;       // E rows per chunk
constexpr int NCH = 5;        // 5*64 = 320 >= 271 band width (c spans 16)
constexpr int STR = 68;       // smem row stride (words); 272B, 16B-aligned
constexpr int SMEM_BYTES = 3 * TM * STR * 4;   // Qs + Es + St = 52224

__device__ __forceinline__ uint32_t f2tf32(float x) {
    uint32_t r;
    asm("cvt.rna.tf32.f32 %0, %1;" : "=r"(r) : "f"(x));
    return r;
}
__device__ __forceinline__ uint32_t smem_u32(const void* p) {
    uint32_t a;
    asm("{ .reg .u64 t; cvta.to.shared.u64 t, %1; cvt.u32.u64 %0, t; }"
        : "=r"(a) : "l"(p));
    return a;
}
__device__ __forceinline__ void cp_async16(uint32_t dst, const void* src) {
    asm volatile("cp.async.ca.shared.global [%0], [%1], 16;"
                 :: "r"(dst), "l"(src));
}
__device__ __forceinline__ void cp_commit() {
    asm volatile("cp.async.commit_group;" ::: "memory");
}
__device__ __forceinline__ void cp_wait0() {
    asm volatile("cp.async.wait_group 0;" ::: "memory");
}

__global__ __launch_bounds__(128, 4)
void srel_tf32_kernel(const float* __restrict__ q,
                      const float* __restrict__ e1,
                      const float* __restrict__ e2,
                      float* __restrict__ out)
{
    extern __shared__ __align__(16) uint32_t smem[];
    uint32_t* Qs = smem;                                   // [64][68] tf32
    float*    Es = reinterpret_cast<float*>(smem + TM * STR);   // [64][68] raw f32
    float*    St = reinterpret_cast<float*>(smem + 2 * TM * STR);

    const int blk  = blockIdx.x;
    const int b    = blk >> 4;            // 16 t-tiles per batch row
    const int t0   = (blk & 15) * TM;
    const int h    = b & 7;
    const int c0   = t0 >> 2;
    const int jbase = 240 - c0;           // min j over tile (c spans c0..c0+15)

    const int tid  = threadIdx.x;
    const int wid  = tid >> 5;
    const int lane = tid & 31;
    const int wt   = wid >> 1;            // t-half: rows [wt*32, +32)
    const int wj   = wid & 1;             // j-half: cols [wj*32, +32)
    const int r    = lane >> 2;
    const int cidx = lane & 3;

    const float4* e1h = reinterpret_cast<const float4*>(e1 + (size_t)h * SS * DD);
    const float4* e2h = reinterpret_cast<const float4*>(e2 + (size_t)h * SS * DD);
    const uint32_t es_base = smem_u32(Es);

    // ---- prefetch E chunk 0 (raw f32, cp.async) ----
    {
        const int jc = jbase;
        for (int i = tid; i < JC * 16; i += 128) {   // 16 x 16B per row
            const int row = i >> 4, c16 = i & 15;
            const int j = jc + row;
            const float4* src;
            if (j <= 255) {
                src = e1h + j * 16 + c16;            // E rows [0,255] = e1
            } else {
                int j2 = j - 255;                    // E rows [256,510] = e2[1:]
                if (j2 > 255) j2 = 255;              // overrun rows never flushed
                src = e2h + j2 * 16 + c16;
            }
            cp_async16(es_base + (row * STR + c16 * 4) * 4, src);
        }
        cp_commit();
    }

    // ---- Q tile (64 x 64) -> smem tf32, float4 loads ----
    const float4* qb4 = reinterpret_cast<const float4*>(
                            q + ((size_t)b * TT + t0) * DD);
    for (int i = tid; i < TM * DD / 4; i += 128) {
        const int row = i >> 4;
        const int k4  = (i & 15) << 2;
        const float4 v = qb4[i];
        uint4 u;
        u.x = f2tf32(v.x); u.y = f2tf32(v.y);
        u.z = f2tf32(v.z); u.w = f2tf32(v.w);
        *reinterpret_cast<uint4*>(Qs + row * STR + k4) = u;
    }

    cp_wait0();
    __syncthreads();

    const uint32_t* Aq = Qs + (wt * 32 + r) * STR + cidx;
    const float*    Be = Es + (wj * 32 + r) * STR + cidx;

    for (int ch = 0; ch < NCH; ch++) {
        // ---- warp 32x32 tile: 2 m-frags x 4 n-frags, K=64 in 8 steps ----
        float acc[2][4][4];
        #pragma unroll
        for (int mt = 0; mt < 2; mt++)
            #pragma unroll
            for (int nt = 0; nt < 4; nt++)
                #pragma unroll
                for (int v = 0; v < 4; v++)
                    acc[mt][nt][v] = 0.0f;

        #pragma unroll
        for (int ks = 0; ks < 8; ks++) {
            const int k0 = ks * 8;
            uint32_t a[2][4], bf[4][2];
            #pragma unroll
            for (int mt = 0; mt < 2; mt++) {
                const uint32_t* p = Aq + mt * 16 * STR + k0;
                a[mt][0] = p[0];
                a[mt][1] = p[8 * STR];
                a[mt][2] = p[4];
                a[mt][3] = p[8 * STR + 4];
            }
            #pragma unroll
            for (int nt = 0; nt < 4; nt++) {
                const float* p = Be + nt * 8 * STR + k0;
                bf[nt][0] = f2tf32(p[0]);
                bf[nt][1] = f2tf32(p[4]);
            }
            #pragma unroll
            for (int mt = 0; mt < 2; mt++)
                #pragma unroll
                for (int nt = 0; nt < 4; nt++)
                    asm volatile(
                        "mma.sync.aligned.m16n8k8.row.col.f32.tf32.tf32.f32 "
                        "{%0,%1,%2,%3}, {%4,%5,%6,%7}, {%8,%9}, {%0,%1,%2,%3};"
                        : "+f"(acc[mt][nt][0]), "+f"(acc[mt][nt][1]),
                          "+f"(acc[mt][nt][2]), "+f"(acc[mt][nt][3])
                        : "r"(a[mt][0]), "r"(a[mt][1]), "r"(a[mt][2]), "r"(a[mt][3]),
                          "r"(bf[nt][0]), "r"(bf[nt][1]));
        }

        __syncthreads();   // all warps finished reading Es (and St flushed)

        // ---- prefetch next E chunk into the freed Es buffer ----
        if (ch < NCH - 1) {
            const int jc = jbase + (ch + 1) * JC;
            for (int i = tid; i < JC * 16; i += 128) {
                const int row = i >> 4, c16 = i & 15;
                const int j = jc + row;
                const float4* src;
                if (j <= 255) {
                    src = e1h + j * 16 + c16;
                } else {
                    int j2 = j - 255;
                    if (j2 > 255) j2 = 255;
                    src = e2h + j2 * 16 + c16;
                }
                cp_async16(es_base + (row * STR + c16 * 4) * 4, src);
            }
            cp_commit();
        }

        // ---- stage: St[row][jj] via STS.64 (overlaps cp.async) ----
        #pragma unroll
        for (int mt = 0; mt < 2; mt++) {
            #pragma unroll
            for (int half = 0; half < 2; half++) {
                const int row = wt * 32 + mt * 16 + half * 8 + r;
                float* srow = St + row * STR + wj * 32 + 2 * cidx;
                #pragma unroll
                for (int nt = 0; nt < 4; nt++) {
                    float2 v;
                    v.x = acc[mt][nt][half * 2 + 0];
                    v.y = acc[mt][nt][half * 2 + 1];
                    *reinterpret_cast<float2*>(srow + nt * 8) = v;
                }
            }
        }
        __syncthreads();   // stage visible

        // ---- coalesced flush: warp owns 16 rows (overlaps cp.async) ----
        {
            const int jc = jbase + ch * JC;
            #pragma unroll
            for (int i = 0; i < 16; i++) {
                const int row  = wid * 16 + i;
                const int c    = (t0 + row) >> 2;
                const int srow = jc + c - 255;
                if (srow >= SS || srow + JC <= 0) continue;
                const float v0 = St[row * STR + lane];
                const float v1 = St[row * STR + 32 + lane];
                const int s0 = srow + lane;
                const int s1 = s0 + 32;
                float* og = out + ((size_t)b * TT + t0 + row) * SS;
                if ((unsigned)s0 < (unsigned)SS) og[s0] = v0;
                if ((unsigned)s1 < (unsigned)SS) og[s1] = v1;
            }
        }

        if (ch < NCH - 1) {
            cp_wait0();
            __syncthreads();   // new Es visible to all warps
        }
    }
}

extern "C" void kernel_launch(void* const* d_in, const int* in_sizes, int n_in,
                              void* d_out, int out_size)
{
    const float* q  = (const float*)d_in[0];
    const float* e1 = (const float*)d_in[1];
    const float* e2 = (const float*)d_in[2];
    float* out      = (float*)d_out;

    cudaFuncSetAttribute(srel_tf32_kernel,
                         cudaFuncAttributeMaxDynamicSharedMemorySize, SMEM_BYTES);
    srel_tf32_kernel<<<128 * (TT / TM), 128, SMEM_BYTES>>>(q, e1, e2, out);
}

// round 7
// speedup vs baseline: 2.1925x; 1.1322x over previous
#include <cuda_runtime.h>
#include <cstdint>

// SubsampledRelativeAttention (closed form, validated R1-R6):
//   h = b % 8, c = t >> 2, E = [e1 ; e2[1:]] (511 rows)
//   out[b,t,s] = q[b,t] . E[h, j],  j = 255 - c + s
// mma.sync m16n8k8 TF32 banded GEMM.
// R7: warp-column tiling (warp = 16 t-rows x 64 j), A fragments held in
// registers across all chunks, warp-private epilogue (no cross-warp stage
// barrier), St aliases Qs -> 36KB smem -> 5 CTAs/SM.

#define TT 1024
#define SS 256
#define DD 64

constexpr int TM   = 64;      // t rows per CTA
constexpr int JC   = 64;      // E rows per chunk
constexpr int NCH  = 5;       // 5*64 = 320 >= 271 band width (c spans 16)
constexpr int STRE = 68;      // Es/Qs stride (words): frag LDS conflict-free
constexpr int STRS = 72;      // St stride (words): STS.64 conflict-free
// St (64x72 floats = 18432B) aliases Qs (64x68 = 17408B): region = max
constexpr int SMEM_BYTES = TM * STRS * 4 + JC * STRE * 4;   // 18432+17408=35840

__device__ __forceinline__ uint32_t f2tf32(float x) {
    uint32_t r;
    asm("cvt.rna.tf32.f32 %0, %1;" : "=r"(r) : "f"(x));
    return r;
}
__device__ __forceinline__ uint32_t smem_u32(const void* p) {
    uint32_t a;
    asm("{ .reg .u64 t; cvta.to.shared.u64 t, %1; cvt.u32.u64 %0, t; }"
        : "=r"(a) : "l"(p));
    return a;
}
__device__ __forceinline__ void cp_async16(uint32_t dst, const void* src) {
    asm volatile("cp.async.ca.shared.global [%0], [%1], 16;"
                 :: "r"(dst), "l"(src));
}
__device__ __forceinline__ void cp_commit() {
    asm volatile("cp.async.commit_group;" ::: "memory");
}
__device__ __forceinline__ void cp_wait0() {
    asm volatile("cp.async.wait_group 0;" ::: "memory");
}

__global__ __launch_bounds__(128, 5)
void srel_tf32_kernel(const float* __restrict__ q,
                      const float* __restrict__ e1,
                      const float* __restrict__ e2,
                      float* __restrict__ out)
{
    extern __shared__ __align__(16) uint32_t smem[];
    uint32_t* Qs = smem;                                     // [64][68] tf32 (init)
    float*    St = reinterpret_cast<float*>(smem);           // [64][72] (aliases Qs)
    float*    Es = reinterpret_cast<float*>(smem + TM * STRS); // [64][68] raw f32

    const int blk  = blockIdx.x;
    const int b    = blk >> 4;            // 16 t-tiles per batch row
    const int t0   = (blk & 15) * TM;
    const int h    = b & 7;
    const int c0   = t0 >> 2;
    const int jbase = 240 - c0;           // min j over tile (c spans c0..c0+15)

    const int tid  = threadIdx.x;
    const int wid  = tid >> 5;
    const int lane = tid & 31;
    const int r    = lane >> 2;
    const int cidx = lane & 3;

    const float4* e1h = reinterpret_cast<const float4*>(e1 + (size_t)h * SS * DD);
    const float4* e2h = reinterpret_cast<const float4*>(e2 + (size_t)h * SS * DD);
    const uint32_t es_base = smem_u32(Es);

    // ---- prefetch E chunk 0 ----
    {
        const int jc = jbase;
        for (int i = tid; i < JC * 16; i += 128) {
            const int row = i >> 4, c16 = i & 15;
            const int j = jc + row;
            const float4* src;
            if (j <= 255) {
                src = e1h + j * 16 + c16;            // E rows [0,255] = e1
            } else {
                int j2 = j - 255;                    // E rows [256,510] = e2[1:]
                if (j2 > 255) j2 = 255;              // overrun rows never flushed
                src = e2h + j2 * 16 + c16;
            }
            cp_async16(es_base + (row * STRE + c16 * 4) * 4, src);
        }
        cp_commit();
    }

    // ---- Q tile (64 x 64) -> smem tf32 ----
    const float4* qb4 = reinterpret_cast<const float4*>(
                            q + ((size_t)b * TT + t0) * DD);
    for (int i = tid; i < TM * DD / 4; i += 128) {
        const int row = i >> 4;
        const int k4  = (i & 15) << 2;
        const float4 v = qb4[i];
        uint4 u;
        u.x = f2tf32(v.x); u.y = f2tf32(v.y);
        u.z = f2tf32(v.z); u.w = f2tf32(v.w);
        *reinterpret_cast<uint4*>(Qs + row * STRE + k4) = u;
    }
    __syncthreads();

    // ---- extract A fragments once: warp owns rows [wid*16, +16) ----
    uint32_t ah[8][4];
    {
        const uint32_t* Aq = Qs + (wid * 16 + r) * STRE + cidx;
        #pragma unroll
        for (int ks = 0; ks < 8; ks++) {
            const int k0 = ks * 8;
            ah[ks][0] = Aq[k0];
            ah[ks][1] = Aq[8 * STRE + k0];
            ah[ks][2] = Aq[k0 + 4];
            ah[ks][3] = Aq[8 * STRE + k0 + 4];
        }
    }
    cp_wait0();
    __syncthreads();   // Qs free (St may be written); Es chunk 0 ready

    const float* Be = Es + r * STRE + cidx;

    for (int ch = 0; ch < NCH; ch++) {
        const int jc = jbase + ch * JC;

        // ---- MMA: warp tile 16t x 64j, 8 n-frags, K=64 in 8 steps ----
        float acc[8][4];
        #pragma unroll
        for (int nt = 0; nt < 8; nt++)
            #pragma unroll
            for (int v = 0; v < 4; v++)
                acc[nt][v] = 0.0f;

        #pragma unroll
        for (int ks = 0; ks < 8; ks++) {
            const int k0 = ks * 8;
            #pragma unroll
            for (int nt = 0; nt < 8; nt++) {
                const float* p = Be + nt * 8 * STRE + k0;
                const uint32_t b0 = f2tf32(p[0]);
                const uint32_t b1 = f2tf32(p[4]);
                asm volatile(
                    "mma.sync.aligned.m16n8k8.row.col.f32.tf32.tf32.f32 "
                    "{%0,%1,%2,%3}, {%4,%5,%6,%7}, {%8,%9}, {%0,%1,%2,%3};"
                    : "+f"(acc[nt][0]), "+f"(acc[nt][1]),
                      "+f"(acc[nt][2]), "+f"(acc[nt][3])
                    : "r"(ah[ks][0]), "r"(ah[ks][1]), "r"(ah[ks][2]), "r"(ah[ks][3]),
                      "r"(b0), "r"(b1));
            }
        }

        __syncthreads();   // all warps done reading Es

        // ---- prefetch next E chunk into freed Es ----
        if (ch < NCH - 1) {
            const int jcn = jbase + (ch + 1) * JC;
            for (int i = tid; i < JC * 16; i += 128) {
                const int row = i >> 4, c16 = i & 15;
                const int j = jcn + row;
                const float4* src;
                if (j <= 255) {
                    src = e1h + j * 16 + c16;
                } else {
                    int j2 = j - 255;
                    if (j2 > 255) j2 = 255;
                    src = e2h + j2 * 16 + c16;
                }
                cp_async16(es_base + (row * STRE + c16 * 4) * 4, src);
            }
            cp_commit();
        }

        // ---- warp-private stage: rows [wid*16, +16), STS.64 conflict-free ----
        #pragma unroll
        for (int half = 0; half < 2; half++) {
            const int row = wid * 16 + half * 8 + r;
            float* srow = St + row * STRS + 2 * cidx;
            #pragma unroll
            for (int nt = 0; nt < 8; nt++) {
                float2 v;
                v.x = acc[nt][half * 2 + 0];
                v.y = acc[nt][half * 2 + 1];
                *reinterpret_cast<float2*>(srow + nt * 8) = v;
            }
        }
        __syncwarp();

        // ---- warp-private coalesced flush ----
        #pragma unroll
        for (int i = 0; i < 16; i++) {
            const int row  = wid * 16 + i;
            const int c    = (t0 + row) >> 2;
            const int srow = jc + c - 255;
            if (srow >= SS || srow + JC <= 0) continue;
            const float v0 = St[row * STRS + lane];
            const float v1 = St[row * STRS + 32 + lane];
            const int s0 = srow + lane;
            const int s1 = s0 + 32;
            float* og = out + ((size_t)b * TT + t0 + row) * SS;
            if ((unsigned)s0 < (unsigned)SS) og[s0] = v0;
            if ((unsigned)s1 < (unsigned)SS) og[s1] = v1;
        }

        if (ch < NCH - 1) {
            cp_wait0();
            __syncthreads();   // next Es visible
        }
    }
}

extern "C" void kernel_launch(void* const* d_in, const int* in_sizes, int n_in,
                              void* d_out, int out_size)
{
    const float* q  = (const float*)d_in[0];
    const float* e1 = (const float*)d_in[1];
    const float* e2 = (const float*)d_in[2];
    float* out      = (float*)d_out;

    cudaFuncSetAttribute(srel_tf32_kernel,
                         cudaFuncAttributeMaxDynamicSharedMemorySize, SMEM_BYTES);
    srel_tf32_kernel<<<128 * (TT / TM), 128, SMEM_BYTES>>>(q, e1, e2, out);
}

// round 8
// speedup vs baseline: 2.3233x; 1.0597x over previous
#include <cuda_runtime.h>
#include <cstdint>

// SubsampledRelativeAttention (closed form, validated R1-R7):
//   h = b % 8, c = t >> 2, E = [e1 ; e2[1:]] (511 rows)
//   out[b,t,s] = q[b,t] . E[h, j],  j = 255 - c + s
// mma.sync m16n8k8 TF32 banded GEMM, warp-column tiling (warp = 16 t x 64 j),
// A fragments register-resident across chunks, warp-private epilogue.
// R8: per-warp fragment skipping (33/40 frags needed per warp), B operand
// fed as raw f32 (tf32 truncation, A stays cvt.rna), cp.async.cg prefetch.

#define TT 1024
#define SS 256
#define DD 64

constexpr int TM   = 64;      // t rows per CTA
constexpr int JC   = 64;      // E rows per chunk
constexpr int NCH  = 5;       // 5*64 = 320 >= 271 band width (c spans 16)
constexpr int STRE = 68;      // Es/Qs stride (words): frag LDS conflict-free
constexpr int STRS = 72;      // St stride (words): STS.64 conflict-free
constexpr int SMEM_BYTES = TM * STRS * 4 + JC * STRE * 4;   // 35840

__device__ __forceinline__ uint32_t f2tf32(float x) {
    uint32_t r;
    asm("cvt.rna.tf32.f32 %0, %1;" : "=r"(r) : "f"(x));
    return r;
}
__device__ __forceinline__ uint32_t smem_u32(const void* p) {
    uint32_t a;
    asm("{ .reg .u64 t; cvta.to.shared.u64 t, %1; cvt.u32.u64 %0, t; }"
        : "=r"(a) : "l"(p));
    return a;
}
__device__ __forceinline__ void cp_async16(uint32_t dst, const void* src) {
    asm volatile("cp.async.cg.shared.global [%0], [%1], 16;"
                 :: "r"(dst), "l"(src));
}
__device__ __forceinline__ void cp_commit() {
    asm volatile("cp.async.commit_group;" ::: "memory");
}
__device__ __forceinline__ void cp_wait0() {
    asm volatile("cp.async.wait_group 0;" ::: "memory");
}

__global__ __launch_bounds__(128, 5)
void srel_tf32_kernel(const float* __restrict__ q,
                      const float* __restrict__ e1,
                      const float* __restrict__ e2,
                      float* __restrict__ out)
{
    extern __shared__ __align__(16) uint32_t smem[];
    uint32_t* Qs = smem;                                       // [64][68] tf32 (init)
    float*    St = reinterpret_cast<float*>(smem);             // [64][72] (aliases Qs)
    uint32_t* Es = smem + TM * STRS;                           // [64][68] raw f32 bits

    const int blk  = blockIdx.x;
    const int b    = blk >> 4;            // 16 t-tiles per batch row
    const int t0   = (blk & 15) * TM;
    const int h    = b & 7;
    const int c0   = t0 >> 2;
    const int jbase = 240 - c0;           // min j over tile (c spans c0..c0+15)

    const int tid  = threadIdx.x;
    const int wid  = tid >> 5;
    const int lane = tid & 31;
    const int r    = lane >> 2;
    const int cidx = lane & 3;

    // per-warp needed global-frag window (frag g covers j in [jbase+8g, +8))
    // warp rows span c in [c0+4w, c0+4w+3] -> j-offset window [12-4w, 270-4w]
    const int glo = (12 - 4 * wid) >> 3;    // 1,1,0,0
    const int ghi = (270 - 4 * wid) >> 3;   // 33,33,32,32

    const float4* e1h = reinterpret_cast<const float4*>(e1 + (size_t)h * SS * DD);
    const float4* e2h = reinterpret_cast<const float4*>(e2 + (size_t)h * SS * DD);
    const uint32_t es_base = smem_u32(Es);

    // ---- prefetch E chunk 0 ----
    {
        const int jc = jbase;
        for (int i = tid; i < JC * 16; i += 128) {
            const int row = i >> 4, c16 = i & 15;
            const int j = jc + row;
            const float4* src;
            if (j <= 255) {
                src = e1h + j * 16 + c16;            // E rows [0,255] = e1
            } else {
                int j2 = j - 255;                    // E rows [256,510] = e2[1:]
                if (j2 > 255) j2 = 255;              // overrun rows never flushed
                src = e2h + j2 * 16 + c16;
            }
            cp_async16(es_base + (row * STRE + c16 * 4) * 4, src);
        }
        cp_commit();
    }

    // ---- Q tile (64 x 64) -> smem tf32 ----
    const float4* qb4 = reinterpret_cast<const float4*>(
                            q + ((size_t)b * TT + t0) * DD);
    for (int i = tid; i < TM * DD / 4; i += 128) {
        const int row = i >> 4;
        const int k4  = (i & 15) << 2;
        const float4 v = qb4[i];
        uint4 u;
        u.x = f2tf32(v.x); u.y = f2tf32(v.y);
        u.z = f2tf32(v.z); u.w = f2tf32(v.w);
        *reinterpret_cast<uint4*>(Qs + row * STRE + k4) = u;
    }
    __syncthreads();

    // ---- extract A fragments once: warp owns rows [wid*16, +16) ----
    uint32_t ah[8][4];
    {
        const uint32_t* Aq = Qs + (wid * 16 + r) * STRE + cidx;
        #pragma unroll
        for (int ks = 0; ks < 8; ks++) {
            const int k0 = ks * 8;
            ah[ks][0] = Aq[k0];
            ah[ks][1] = Aq[8 * STRE + k0];
            ah[ks][2] = Aq[k0 + 4];
            ah[ks][3] = Aq[8 * STRE + k0 + 4];
        }
    }
    cp_wait0();
    __syncthreads();   // Qs free (St may be written); Es chunk 0 ready

    const uint32_t* Be = Es + r * STRE + cidx;

    for (int ch = 0; ch < NCH; ch++) {
        const int jc    = jbase + ch * JC;
        const int gbase = ch * 8;

        // ---- MMA: warp tile 16t x 64j, only frags in warp band ----
        float acc[8][4];
        #pragma unroll
        for (int nt = 0; nt < 8; nt++)
            #pragma unroll
            for (int v = 0; v < 4; v++)
                acc[nt][v] = 0.0f;

        #pragma unroll
        for (int nt = 0; nt < 8; nt++) {
            const int g = gbase + nt;
            if (g < glo || g > ghi) continue;     // warp-uniform skip
            const uint32_t* p = Be + nt * 8 * STRE;
            #pragma unroll
            for (int ks = 0; ks < 8; ks++) {
                const uint32_t b0 = p[ks * 8];        // raw f32 -> tf32 truncation
                const uint32_t b1 = p[ks * 8 + 4];
                asm volatile(
                    "mma.sync.aligned.m16n8k8.row.col.f32.tf32.tf32.f32 "
                    "{%0,%1,%2,%3}, {%4,%5,%6,%7}, {%8,%9}, {%0,%1,%2,%3};"
                    : "+f"(acc[nt][0]), "+f"(acc[nt][1]),
                      "+f"(acc[nt][2]), "+f"(acc[nt][3])
                    : "r"(ah[ks][0]), "r"(ah[ks][1]), "r"(ah[ks][2]), "r"(ah[ks][3]),
                      "r"(b0), "r"(b1));
            }
        }

        __syncthreads();   // all warps done reading Es

        // ---- prefetch next E chunk into freed Es ----
        if (ch < NCH - 1) {
            const int jcn = jbase + (ch + 1) * JC;
            for (int i = tid; i < JC * 16; i += 128) {
                const int row = i >> 4, c16 = i & 15;
                const int j = jcn + row;
                const float4* src;
                if (j <= 255) {
                    src = e1h + j * 16 + c16;
                } else {
                    int j2 = j - 255;
                    if (j2 > 255) j2 = 255;
                    src = e2h + j2 * 16 + c16;
                }
                cp_async16(es_base + (row * STRE + c16 * 4) * 4, src);
            }
            cp_commit();
        }

        // ---- warp-private stage (skip out-of-band frags) ----
        #pragma unroll
        for (int half = 0; half < 2; half++) {
            const int row = wid * 16 + half * 8 + r;
            float* srow = St + row * STRS + 2 * cidx;
            #pragma unroll
            for (int nt = 0; nt < 8; nt++) {
                const int g = gbase + nt;
                if (g < glo || g > ghi) continue;
                float2 v;
                v.x = acc[nt][half * 2 + 0];
                v.y = acc[nt][half * 2 + 1];
                *reinterpret_cast<float2*>(srow + nt * 8) = v;
            }
        }
        __syncwarp();

        // ---- warp-private coalesced flush ----
        #pragma unroll
        for (int i = 0; i < 16; i++) {
            const int row  = wid * 16 + i;
            const int c    = (t0 + row) >> 2;
            const int srow = jc + c - 255;
            if (srow >= SS || srow + JC <= 0) continue;
            const float v0 = St[row * STRS + lane];
            const float v1 = St[row * STRS + 32 + lane];
            const int s0 = srow + lane;
            const int s1 = s0 + 32;
            float* og = out + ((size_t)b * TT + t0 + row) * SS;
            if ((unsigned)s0 < (unsigned)SS) og[s0] = v0;
            if ((unsigned)s1 < (unsigned)SS) og[s1] = v1;
        }

        if (ch < NCH - 1) {
            cp_wait0();
            __syncthreads();   // next Es visible
        }
    }
}

extern "C" void kernel_launch(void* const* d_in, const int* in_sizes, int n_in,
                              void* d_out, int out_size)
{
    const float* q  = (const float*)d_in[0];
    const float* e1 = (const float*)d_in[1];
    const float* e2 = (const float*)d_in[2];
    float* out      = (float*)d_out;

    cudaFuncSetAttribute(srel_tf32_kernel,
                         cudaFuncAttributeMaxDynamicSharedMemorySize, SMEM_BYTES);
    srel_tf32_kernel<<<128 * (TT / TM), 128, SMEM_BYTES>>>(q, e1, e2, out);
}